// round 14
// baseline (speedup 1.0000x reference)
#include <cuda_runtime.h>
#include <cuda_fp16.h>
#include <cstdint>

#define NB 32
#define NS 8192
#define ND 64
#define NSPLIT 16
#define ROWS (NS / NSPLIT)   // 512 seq rows per CTA
#define BK 32                // seq rows per smem stage
#define NSTAGE (ROWS / BK)   // 16
#define KP 16                // half2 k-pair rows per stage
#define DP2 72               // words per kpair row (64 + 8 pad): CF frag LDS
#define MATW (KP * DP2)      // 1152 words per matrix per buffer

// Partial results: [NSPLIT][NB][2][64][64]  (mat0 = rr+ii, mat1 = ri - ri^T)
__device__ __align__(16) float g_scratch[NSPLIT * NB * 2 * ND * ND];
// Per-batch arrival counters (zero-init; reset by the reducing CTA each launch).
__device__ int g_counter[NB];

// Pack two floats into f16x2: lo -> low half (smaller k), hi -> high half.
__device__ __forceinline__ unsigned pk(float lo, float hi) {
    unsigned u;
    asm("cvt.rn.f16x2.f32 %0, %1, %2;" : "=r"(u) : "f"(hi), "f"(lo));
    return u;
}

// NOT volatile: ptxas may interleave/schedule MMAs. K=16 per instruction.
__device__ __forceinline__ void mma_f16(float c[4],
                                        unsigned a0, unsigned a1, unsigned a2, unsigned a3,
                                        unsigned b0, unsigned b1) {
    asm("mma.sync.aligned.m16n8k16.row.col.f32.f16.f16.f32 "
        "{%0,%1,%2,%3}, {%4,%5,%6,%7}, {%8,%9}, {%0,%1,%2,%3};"
        : "+f"(c[0]), "+f"(c[1]), "+f"(c[2]), "+f"(c[3])
        : "r"(a0), "r"(a1), "r"(a2), "r"(a3), "r"(b0), "r"(b1));
}

__global__ __launch_bounds__(128, 4) void gram_kernel(const float* __restrict__ gr,
                                                      const float* __restrict__ gi,
                                                      float* __restrict__ out) {
    // Main loop: [2 buf][3 mat: R,I,C][KP][DP2] u32 = 6912 words (27.6 KB).
    // Epilogue reuses as sA[64][65] + sM[64][65] = 8320 floats.
    __shared__ __align__(16) float s_raw[8320];
    __shared__ int s_last;
    unsigned* const sw = (unsigned*)s_raw;

    const int b    = blockIdx.x >> 4;           // NSPLIT = 16
    const int sp   = blockIdx.x & (NSPLIT - 1);
    const int tid  = threadIdx.x;
    const int L    = tid & 31;
    const int warp = tid >> 5;                  // 0..3
    const int g    = L >> 2;
    const int t    = L & 3;
    const int m0w  = (warp & 1) * 32;           // warp's 32-row m block
    const int n0w  = (warp >> 1) * 32;          // warp's 32-col n block

    const float* baseR = gr + ((long)b * NS + (long)sp * ROWS) * ND;
    const float* baseI = gi + ((long)b * NS + (long)sp * ROWS) * ND;

    float accG[2][4][4];  // G = C^T C  (C = R + I)
    float accM[2][4][4];  // M = R^T I
#pragma unroll
    for (int bd = 0; bd < 2; bd++)
#pragma unroll
        for (int jj = 0; jj < 4; jj++)
#pragma unroll
            for (int c = 0; c < 4; c++) { accG[bd][jj][c] = 0.f; accM[bd][jj][c] = 0.f; }

    // Producer unit u = tid + h*128: kpair p = u>>4 (0..15), d-quad q = u&15.
    float4 rv0, rv1, iv0, iv1;

#define LOADC(st_, h_) do {                                                    \
        const int u_ = tid + (h_) * 128;                                       \
        const int p_ = u_ >> 4, q_ = u_ & 15;                                  \
        const long oA_ = ((long)(st_) * BK + 2 * p_) * ND + 4 * q_;            \
        rv0 = *(const float4*)(baseR + oA_);                                   \
        rv1 = *(const float4*)(baseR + oA_ + ND);                              \
        iv0 = *(const float4*)(baseI + oA_);                                   \
        iv1 = *(const float4*)(baseI + oA_ + ND);                              \
    } while (0)

    // Store R, I, and C = R+I (computed fp32, single rounding to f16).
#define STSC(buf_, h_) do {                                                    \
        const int u_ = tid + (h_) * 128;                                       \
        const int p_ = u_ >> 4, q_ = u_ & 15;                                  \
        unsigned* bp_ = sw + (buf_) * 3 * MATW + p_ * DP2 + 4 * q_;            \
        *(uint4*)bp_ = make_uint4(pk(rv0.x, rv1.x), pk(rv0.y, rv1.y),          \
                                  pk(rv0.z, rv1.z), pk(rv0.w, rv1.w));         \
        *(uint4*)(bp_ + MATW) = make_uint4(pk(iv0.x, iv1.x), pk(iv0.y, iv1.y), \
                                           pk(iv0.z, iv1.z), pk(iv0.w, iv1.w)); \
        *(uint4*)(bp_ + 2 * MATW) = make_uint4(                                \
            pk(rv0.x + iv0.x, rv1.x + iv1.x), pk(rv0.y + iv0.y, rv1.y + iv1.y), \
            pk(rv0.z + iv0.z, rv1.z + iv1.z), pk(rv0.w + iv0.w, rv1.w + iv1.w)); \
    } while (0)

    // One k16-step: 32 frag LDS (conflict-free) + 16 MMAs, all distinct accs.
#define COMP(cR_, cI_, cC_, s_) do {                                           \
        const int kb_ = 8 * (s_);                                              \
        const unsigned* pr0_ = (cR_) + (kb_ + t) * DP2;                        \
        const unsigned* pr1_ = (cR_) + (kb_ + t + 4) * DP2;                    \
        const unsigned* pi0_ = (cI_) + (kb_ + t) * DP2;                        \
        const unsigned* pi1_ = (cI_) + (kb_ + t + 4) * DP2;                    \
        const unsigned* pc0_ = (cC_) + (kb_ + t) * DP2;                        \
        const unsigned* pc1_ = (cC_) + (kb_ + t + 4) * DP2;                    \
        unsigned aC_[2][4], aR_[2][4];                                         \
        _Pragma("unroll")                                                      \
        for (int bd_ = 0; bd_ < 2; bd_++) {                                    \
            const int m_ = m0w + 16 * bd_ + g;                                 \
            aC_[bd_][0] = pc0_[m_];  aC_[bd_][1] = pc0_[m_ + 8];               \
            aC_[bd_][2] = pc1_[m_];  aC_[bd_][3] = pc1_[m_ + 8];               \
            aR_[bd_][0] = pr0_[m_];  aR_[bd_][1] = pr0_[m_ + 8];               \
            aR_[bd_][2] = pr1_[m_];  aR_[bd_][3] = pr1_[m_ + 8];               \
        }                                                                      \
        unsigned bc0_[4], bc1_[4], bi0_[4], bi1_[4];                           \
        _Pragma("unroll")                                                      \
        for (int j_ = 0; j_ < 4; j_++) {                                       \
            const int n_ = n0w + j_ * 8 + g;                                   \
            bc0_[j_] = pc0_[n_];  bc1_[j_] = pc1_[n_];                         \
            bi0_[j_] = pi0_[n_];  bi1_[j_] = pi1_[n_];                         \
        }                                                                      \
        _Pragma("unroll")                                                      \
        for (int bd_ = 0; bd_ < 2; bd_++)                                      \
            _Pragma("unroll")                                                  \
            for (int j_ = 0; j_ < 4; j_++) {                                   \
                mma_f16(accG[bd_][j_], aC_[bd_][0], aC_[bd_][1],               \
                        aC_[bd_][2], aC_[bd_][3], bc0_[j_], bc1_[j_]);         \
                mma_f16(accM[bd_][j_], aR_[bd_][0], aR_[bd_][1],               \
                        aR_[bd_][2], aR_[bd_][3], bi0_[j_], bi1_[j_]);         \
            }                                                                  \
    } while (0)

    // ---- prologue: stage 0 into buffer 0 ----
    LOADC(0, 0); STSC(0, 0);
    LOADC(0, 1); STSC(0, 1);
    __syncthreads();

#pragma unroll 1
    for (int st = 0; st < NSTAGE; st++) {
        const int cur = st & 1;
        const int nxt = cur ^ 1;
        const bool more = (st + 1 < NSTAGE);
        const unsigned* cR = sw + cur * 3 * MATW;
        const unsigned* cI = cR + MATW;
        const unsigned* cC = cI + MATW;

        if (more) LOADC(st + 1, 0);
        COMP(cR, cI, cC, 0);
        if (more) { STSC(nxt, 0); LOADC(st + 1, 1); }
        COMP(cR, cI, cC, 1);
        if (more) STSC(nxt, 1);
        __syncthreads();
    }

    // ---- epilogue: stage G and M through smem, combine, write 2 matrices ----
    // C frag map: c0:(r,2t) c1:(r,2t+1) c2:(r+8,2t) c3:(r+8,2t+1)
    float* const sA = s_raw;             // [64][65] G
    float* const sM = s_raw + ND * 65;   // [64][65] M
#pragma unroll
    for (int bd = 0; bd < 2; bd++)
#pragma unroll
        for (int jj = 0; jj < 4; jj++) {
            const int r0 = m0w + bd * 16 + g;
            const int r1 = r0 + 8;
            const int n  = n0w + jj * 8 + 2 * t;
            sA[r0 * 65 + n]     = accG[bd][jj][0];
            sA[r0 * 65 + n + 1] = accG[bd][jj][1];
            sA[r1 * 65 + n]     = accG[bd][jj][2];
            sA[r1 * 65 + n + 1] = accG[bd][jj][3];
            sM[r0 * 65 + n]     = accM[bd][jj][0];
            sM[r0 * 65 + n + 1] = accM[bd][jj][1];
            sM[r1 * 65 + n]     = accM[bd][jj][2];
            sM[r1 * 65 + n + 1] = accM[bd][jj][3];
        }
    __syncthreads();

    float* const base = g_scratch + ((long)(sp * NB + b) * 2 << 12);
#pragma unroll
    for (int it = 0; it < 8; it++) {
        const int idx = it * 128 + tid;    // 0..1023
        const int row = idx >> 4;
        const int col = (idx & 15) * 4;
        float4 v0, v1;
        // mat0 = G - M - M^T (= rr + ii), mat1 = M - M^T (= ri - ri^T).
#pragma unroll
        for (int e = 0; e < 4; e++) {
            const float mm = sM[row * 65 + col + e];
            const float mt = sM[(col + e) * 65 + row];
            const float gg = sA[row * 65 + col + e];
            (&v0.x)[e] = gg - mm - mt;
            (&v1.x)[e] = mm - mt;
        }
        *(float4*)(base +        row * ND + col) = v0;   // mat0 = rr+ii
        *(float4*)(base + 4096 + row * ND + col) = v1;   // mat1 = ri - ri^T
    }

    // ---- fused final reduction: last CTA of each batch sums the partials ----
    __threadfence();        // make this CTA's partials visible device-wide
    __syncthreads();
    if (tid == 0)
        s_last = (atomicAdd(&g_counter[b], 1) == NSPLIT - 1);
    __syncthreads();
    if (s_last) {
        // Sum 16 chunks in fixed order (deterministic); partials are L2-hot.
        const float inv = 1.0f / (float)NS;
#pragma unroll 1
        for (int it = 0; it < 16; it++) {
            const int f4 = it * 128 + tid;       // 0..2047 float4 of batch b
            const int ij = f4 << 2;              // 0..8191
            const int m  = ij >> 12;             // 0 = real, 1 = imag
            const int o  = ij & 4095;
            const float* p = g_scratch + (((long)(b * 2 + m)) << 12) + o;
            float4 a = *(const float4*)p;
#pragma unroll
            for (int spp = 1; spp < NSPLIT; spp++) {
                const float4 v = *(const float4*)(p + (long)spp * (NB * 2 * 4096));
                a.x += v.x; a.y += v.y; a.z += v.z; a.w += v.w;
            }
            *(float4*)(out + (long)m * (NB * ND * ND) + b * (ND * ND) + o) =
                make_float4(a.x * inv, a.y * inv, a.z * inv, a.w * inv);
        }
        if (tid == 0) g_counter[b] = 0;          // reset for next graph replay
    }
}

extern "C" void kernel_launch(void* const* d_in, const int* in_sizes, int n_in,
                              void* d_out, int out_size) {
    const float* input_real = (const float*)d_in[0];
    const float* input_imag = (const float*)d_in[1];
    float* out = (float*)d_out;

    gram_kernel<<<NB * NSPLIT, 128>>>(input_real, input_imag, out);

    (void)in_sizes; (void)n_in; (void)out_size;
}

// round 15
// speedup vs baseline: 1.0359x; 1.0359x over previous
#include <cuda_runtime.h>
#include <cuda_fp16.h>
#include <cstdint>

#define NB 32
#define NS 8192
#define ND 64
#define NSPLIT 16
#define ROWS (NS / NSPLIT)   // 512 seq rows per CTA
#define BK 32                // seq rows per smem stage
#define NSTAGE (ROWS / BK)   // 16
#define KP 16                // half2 k-pair rows per stage
#define DP2 72               // words per kpair row (64 + 8 pad): CF frag LDS
#define MATW (KP * DP2)      // 1152 words per matrix per buffer

// Partial results: [NSPLIT][NB][2][64][64]  (mat0 = rr+ii, mat1 = ri - ri^T)
__device__ __align__(16) float g_scratch[NSPLIT * NB * 2 * ND * ND];

// Pack two floats into f16x2: lo -> low half (smaller k), hi -> high half.
__device__ __forceinline__ unsigned pk(float lo, float hi) {
    unsigned u;
    asm("cvt.rn.f16x2.f32 %0, %1, %2;" : "=r"(u) : "f"(hi), "f"(lo));
    return u;
}

// NOT volatile: ptxas may interleave/schedule MMAs. K=16 per instruction.
__device__ __forceinline__ void mma_f16(float c[4],
                                        unsigned a0, unsigned a1, unsigned a2, unsigned a3,
                                        unsigned b0, unsigned b1) {
    asm("mma.sync.aligned.m16n8k16.row.col.f32.f16.f16.f32 "
        "{%0,%1,%2,%3}, {%4,%5,%6,%7}, {%8,%9}, {%0,%1,%2,%3};"
        : "+f"(c[0]), "+f"(c[1]), "+f"(c[2]), "+f"(c[3])
        : "r"(a0), "r"(a1), "r"(a2), "r"(a3), "r"(b0), "r"(b1));
}

// 5 CTAs/SM: reg cap ~102 -> 20 warps/SM (occ 31% vs 21% at 4 CTAs).
__global__ __launch_bounds__(128, 5) void gram_kernel(const float* __restrict__ gr,
                                                      const float* __restrict__ gi) {
    // Main loop: [2 buf][3 mat: R,I,C][KP][DP2] u32 = 6912 words (27.6 KB).
    // Epilogue reuses as sA[64][65] + sM[64][65] = 8320 floats.
    __shared__ __align__(16) float s_raw[8320];
    unsigned* const sw = (unsigned*)s_raw;

    const int b    = blockIdx.x >> 4;           // NSPLIT = 16
    const int sp   = blockIdx.x & (NSPLIT - 1);
    const int tid  = threadIdx.x;
    const int L    = tid & 31;
    const int warp = tid >> 5;                  // 0..3
    const int g    = L >> 2;
    const int t    = L & 3;
    const int m0w  = (warp & 1) * 32;           // warp's 32-row m block
    const int n0w  = (warp >> 1) * 32;          // warp's 32-col n block

    const float* baseR = gr + ((long)b * NS + (long)sp * ROWS) * ND;
    const float* baseI = gi + ((long)b * NS + (long)sp * ROWS) * ND;

    float accG[2][4][4];  // G = C^T C  (C = R + I)
    float accM[2][4][4];  // M = R^T I
#pragma unroll
    for (int bd = 0; bd < 2; bd++)
#pragma unroll
        for (int jj = 0; jj < 4; jj++)
#pragma unroll
            for (int c = 0; c < 4; c++) { accG[bd][jj][c] = 0.f; accM[bd][jj][c] = 0.f; }

    // Producer unit u = tid + h*128: kpair p = u>>4 (0..15), d-quad q = u&15.
    float4 rv0, rv1, iv0, iv1;

#define LOADC(st_, h_) do {                                                    \
        const int u_ = tid + (h_) * 128;                                       \
        const int p_ = u_ >> 4, q_ = u_ & 15;                                  \
        const long oA_ = ((long)(st_) * BK + 2 * p_) * ND + 4 * q_;            \
        rv0 = *(const float4*)(baseR + oA_);                                   \
        rv1 = *(const float4*)(baseR + oA_ + ND);                              \
        iv0 = *(const float4*)(baseI + oA_);                                   \
        iv1 = *(const float4*)(baseI + oA_ + ND);                              \
    } while (0)

    // Store R, I, and C = R+I (computed fp32, single rounding to f16).
#define STSC(buf_, h_) do {                                                    \
        const int u_ = tid + (h_) * 128;                                       \
        const int p_ = u_ >> 4, q_ = u_ & 15;                                  \
        unsigned* bp_ = sw + (buf_) * 3 * MATW + p_ * DP2 + 4 * q_;            \
        *(uint4*)bp_ = make_uint4(pk(rv0.x, rv1.x), pk(rv0.y, rv1.y),          \
                                  pk(rv0.z, rv1.z), pk(rv0.w, rv1.w));         \
        *(uint4*)(bp_ + MATW) = make_uint4(pk(iv0.x, iv1.x), pk(iv0.y, iv1.y), \
                                           pk(iv0.z, iv1.z), pk(iv0.w, iv1.w)); \
        *(uint4*)(bp_ + 2 * MATW) = make_uint4(                                \
            pk(rv0.x + iv0.x, rv1.x + iv1.x), pk(rv0.y + iv0.y, rv1.y + iv1.y), \
            pk(rv0.z + iv0.z, rv1.z + iv1.z), pk(rv0.w + iv0.w, rv1.w + iv1.w)); \
    } while (0)

    // One k16-step: A-frags held (16 regs), B-frags loaded per-j (4 live regs).
#define COMP(cR_, cI_, cC_, s_) do {                                           \
        const int kb_ = 8 * (s_);                                              \
        const unsigned* pi0_ = (cI_) + (kb_ + t) * DP2;                        \
        const unsigned* pi1_ = (cI_) + (kb_ + t + 4) * DP2;                    \
        const unsigned* pc0_ = (cC_) + (kb_ + t) * DP2;                        \
        const unsigned* pc1_ = (cC_) + (kb_ + t + 4) * DP2;                    \
        const unsigned* pr0_ = (cR_) + (kb_ + t) * DP2;                        \
        const unsigned* pr1_ = (cR_) + (kb_ + t + 4) * DP2;                    \
        unsigned aC_[2][4], aR_[2][4];                                         \
        _Pragma("unroll")                                                      \
        for (int bd_ = 0; bd_ < 2; bd_++) {                                    \
            const int m_ = m0w + 16 * bd_ + g;                                 \
            aC_[bd_][0] = pc0_[m_];  aC_[bd_][1] = pc0_[m_ + 8];               \
            aC_[bd_][2] = pc1_[m_];  aC_[bd_][3] = pc1_[m_ + 8];               \
            aR_[bd_][0] = pr0_[m_];  aR_[bd_][1] = pr0_[m_ + 8];               \
            aR_[bd_][2] = pr1_[m_];  aR_[bd_][3] = pr1_[m_ + 8];               \
        }                                                                      \
        _Pragma("unroll")                                                      \
        for (int j_ = 0; j_ < 4; j_++) {                                       \
            const int n_ = n0w + j_ * 8 + g;                                   \
            const unsigned bc0_ = pc0_[n_];                                    \
            const unsigned bc1_ = pc1_[n_];                                    \
            const unsigned bi0_ = pi0_[n_];                                    \
            const unsigned bi1_ = pi1_[n_];                                    \
            _Pragma("unroll")                                                  \
            for (int bd_ = 0; bd_ < 2; bd_++) {                                \
                mma_f16(accG[bd_][j_], aC_[bd_][0], aC_[bd_][1],               \
                        aC_[bd_][2], aC_[bd_][3], bc0_, bc1_);                 \
                mma_f16(accM[bd_][j_], aR_[bd_][0], aR_[bd_][1],               \
                        aR_[bd_][2], aR_[bd_][3], bi0_, bi1_);                 \
            }                                                                  \
        }                                                                      \
    } while (0)

    // ---- prologue: stage 0 into buffer 0 ----
    LOADC(0, 0); STSC(0, 0);
    LOADC(0, 1); STSC(0, 1);
    __syncthreads();

#pragma unroll 1
    for (int st = 0; st < NSTAGE; st++) {
        const int cur = st & 1;
        const int nxt = cur ^ 1;
        const bool more = (st + 1 < NSTAGE);
        const unsigned* cR = sw + cur * 3 * MATW;
        const unsigned* cI = cR + MATW;
        const unsigned* cC = cI + MATW;

        if (more) LOADC(st + 1, 0);
        COMP(cR, cI, cC, 0);
        if (more) { STSC(nxt, 0); LOADC(st + 1, 1); }
        COMP(cR, cI, cC, 1);
        if (more) STSC(nxt, 1);
        __syncthreads();
    }

    // ---- epilogue: stage G and M through smem, combine, write 2 matrices ----
    // C frag map: c0:(r,2t) c1:(r,2t+1) c2:(r+8,2t) c3:(r+8,2t+1)
    float* const sA = s_raw;             // [64][65] G
    float* const sM = s_raw + ND * 65;   // [64][65] M
#pragma unroll
    for (int bd = 0; bd < 2; bd++)
#pragma unroll
        for (int jj = 0; jj < 4; jj++) {
            const int r0 = m0w + bd * 16 + g;
            const int r1 = r0 + 8;
            const int n  = n0w + jj * 8 + 2 * t;
            sA[r0 * 65 + n]     = accG[bd][jj][0];
            sA[r0 * 65 + n + 1] = accG[bd][jj][1];
            sA[r1 * 65 + n]     = accG[bd][jj][2];
            sA[r1 * 65 + n + 1] = accG[bd][jj][3];
            sM[r0 * 65 + n]     = accM[bd][jj][0];
            sM[r0 * 65 + n + 1] = accM[bd][jj][1];
            sM[r1 * 65 + n]     = accM[bd][jj][2];
            sM[r1 * 65 + n + 1] = accM[bd][jj][3];
        }
    __syncthreads();

    float* const base = g_scratch + ((long)(sp * NB + b) * 2 << 12);
#pragma unroll
    for (int it = 0; it < 8; it++) {
        const int idx = it * 128 + tid;    // 0..1023
        const int row = idx >> 4;
        const int col = (idx & 15) * 4;
        float4 v0, v1;
        // mat0 = G - M - M^T (= rr + ii), mat1 = M - M^T (= ri - ri^T).
#pragma unroll
        for (int e = 0; e < 4; e++) {
            const float mm = sM[row * 65 + col + e];
            const float mt = sM[(col + e) * 65 + row];
            const float gg = sA[row * 65 + col + e];
            (&v0.x)[e] = gg - mm - mt;
            (&v1.x)[e] = mm - mt;
        }
        *(float4*)(base +        row * ND + col) = v0;   // mat0 = rr+ii
        *(float4*)(base + 4096 + row * ND + col) = v1;   // mat1 = ri - ri^T
    }
}

__global__ __launch_bounds__(256) void reduce_kernel(float* __restrict__ out) {
    // One float per thread: 262144 threads. Branch-free single-stream sum.
    const int f   = blockIdx.x * blockDim.x + threadIdx.x;
    const int b   = f >> 13;        // 8192 floats per batch (2 output mats)
    const int rem = f & 8191;
    const int m   = rem >> 12;      // 0 = real, 1 = imag (uniform per block)
    const int ij  = rem & 4095;

    const float* p = g_scratch + (((long)(b * 2 + m)) << 12) + ij;
    float a = 0.f;
#pragma unroll
    for (int sp = 0; sp < NSPLIT; sp++)
        a += __ldcg(p + (long)sp * (NB * 2 * 4096));
    out[(long)m * (NB * ND * ND) + b * (ND * ND) + ij] = a * (1.0f / (float)NS);
}

extern "C" void kernel_launch(void* const* d_in, const int* in_sizes, int n_in,
                              void* d_out, int out_size) {
    const float* input_real = (const float*)d_in[0];
    const float* input_imag = (const float*)d_in[1];
    float* out = (float*)d_out;

    gram_kernel<<<NB * NSPLIT, 128>>>(input_real, input_imag);
    reduce_kernel<<<1024, 256>>>(out);

    (void)in_sizes; (void)n_in; (void)out_size;
}

// round 17
// speedup vs baseline: 1.3043x; 1.2591x over previous
#include <cuda_runtime.h>
#include <cuda_fp16.h>
#include <cstdint>

#define NB 32
#define NS 8192
#define ND 64
#define NSPLIT 16
#define ROWS (NS / NSPLIT)   // 512 seq rows per CTA
#define BK 32                // seq rows per smem stage
#define NSTAGE (ROWS / BK)   // 16
#define KP 16                // half2 k-pair rows per stage
#define DP2 72               // words per kpair row (64 + 8 pad): CF frag LDS
#define MATW (KP * DP2)      // 1152 words per matrix per buffer

// Partial results in f16x2: [NSPLIT][NB][2][2048]  (2048 half2 = 64x64 halves)
// mat0 = rr+ii, mat1 = ri - ri^T. 8 MB total.
__device__ __align__(16) unsigned g_scratch[NSPLIT * NB * 2 * 2048];

// Pack two floats into f16x2: lo -> low half, hi -> high half.
__device__ __forceinline__ unsigned pk(float lo, float hi) {
    unsigned u;
    asm("cvt.rn.f16x2.f32 %0, %1, %2;" : "=r"(u) : "f"(hi), "f"(lo));
    return u;
}

// NOT volatile: ptxas may interleave/schedule MMAs. K=16 per instruction.
__device__ __forceinline__ void mma_f16(float c[4],
                                        unsigned a0, unsigned a1, unsigned a2, unsigned a3,
                                        unsigned b0, unsigned b1) {
    asm("mma.sync.aligned.m16n8k16.row.col.f32.f16.f16.f32 "
        "{%0,%1,%2,%3}, {%4,%5,%6,%7}, {%8,%9}, {%0,%1,%2,%3};"
        : "+f"(c[0]), "+f"(c[1]), "+f"(c[2]), "+f"(c[3])
        : "r"(a0), "r"(a1), "r"(a2), "r"(a3), "r"(b0), "r"(b1));
}

__global__ __launch_bounds__(128, 4) void gram_kernel(const float* __restrict__ gr,
                                                      const float* __restrict__ gi) {
    // Main loop: [2 buf][3 mat: R,I,C][KP][DP2] u32 = 6912 words (27.6 KB).
    // Epilogue reuses as sA[64][65] + sM[64][65] = 8320 floats.
    __shared__ __align__(16) float s_raw[8320];
    unsigned* const sw = (unsigned*)s_raw;

    const int b    = blockIdx.x >> 4;           // NSPLIT = 16
    const int sp   = blockIdx.x & (NSPLIT - 1);
    const int tid  = threadIdx.x;
    const int L    = tid & 31;
    const int warp = tid >> 5;                  // 0..3
    const int g    = L >> 2;
    const int t    = L & 3;
    const int m0w  = (warp & 1) * 32;           // warp's 32-row m block
    const int n0w  = (warp >> 1) * 32;          // warp's 32-col n block

    const float* baseR = gr + ((long)b * NS + (long)sp * ROWS) * ND;
    const float* baseI = gi + ((long)b * NS + (long)sp * ROWS) * ND;

    float accG[2][4][4];  // G = C^T C  (C = R + I)
    float accM[2][4][4];  // M = R^T I
#pragma unroll
    for (int bd = 0; bd < 2; bd++)
#pragma unroll
        for (int jj = 0; jj < 4; jj++)
#pragma unroll
            for (int c = 0; c < 4; c++) { accG[bd][jj][c] = 0.f; accM[bd][jj][c] = 0.f; }

    // Producer unit u = tid + h*128: kpair p = u>>4 (0..15), d-quad q = u&15.
    float4 rv0, rv1, iv0, iv1;

#define LOADC(st_, h_) do {                                                    \
        const int u_ = tid + (h_) * 128;                                       \
        const int p_ = u_ >> 4, q_ = u_ & 15;                                  \
        const long oA_ = ((long)(st_) * BK + 2 * p_) * ND + 4 * q_;            \
        rv0 = *(const float4*)(baseR + oA_);                                   \
        rv1 = *(const float4*)(baseR + oA_ + ND);                              \
        iv0 = *(const float4*)(baseI + oA_);                                   \
        iv1 = *(const float4*)(baseI + oA_ + ND);                              \
    } while (0)

    // Store R, I, and C = R+I (computed fp32, single rounding to f16).
#define STSC(buf_, h_) do {                                                    \
        const int u_ = tid + (h_) * 128;                                       \
        const int p_ = u_ >> 4, q_ = u_ & 15;                                  \
        unsigned* bp_ = sw + (buf_) * 3 * MATW + p_ * DP2 + 4 * q_;            \
        *(uint4*)bp_ = make_uint4(pk(rv0.x, rv1.x), pk(rv0.y, rv1.y),          \
                                  pk(rv0.z, rv1.z), pk(rv0.w, rv1.w));         \
        *(uint4*)(bp_ + MATW) = make_uint4(pk(iv0.x, iv1.x), pk(iv0.y, iv1.y), \
                                           pk(iv0.z, iv1.z), pk(iv0.w, iv1.w)); \
        *(uint4*)(bp_ + 2 * MATW) = make_uint4(                                \
            pk(rv0.x + iv0.x, rv1.x + iv1.x), pk(rv0.y + iv0.y, rv1.y + iv1.y), \
            pk(rv0.z + iv0.z, rv1.z + iv1.z), pk(rv0.w + iv0.w, rv1.w + iv1.w)); \
    } while (0)

    // One k16-step: 32 frag LDS (conflict-free) + 16 MMAs, all distinct accs.
#define COMP(cR_, cI_, cC_, s_) do {                                           \
        const int kb_ = 8 * (s_);                                              \
        const unsigned* pr0_ = (cR_) + (kb_ + t) * DP2;                        \
        const unsigned* pr1_ = (cR_) + (kb_ + t + 4) * DP2;                    \
        const unsigned* pi0_ = (cI_) + (kb_ + t) * DP2;                        \
        const unsigned* pi1_ = (cI_) + (kb_ + t + 4) * DP2;                    \
        const unsigned* pc0_ = (cC_) + (kb_ + t) * DP2;                        \
        const unsigned* pc1_ = (cC_) + (kb_ + t + 4) * DP2;                    \
        unsigned aC_[2][4], aR_[2][4];                                         \
        _Pragma("unroll")                                                      \
        for (int bd_ = 0; bd_ < 2; bd_++) {                                    \
            const int m_ = m0w + 16 * bd_ + g;                                 \
            aC_[bd_][0] = pc0_[m_];  aC_[bd_][1] = pc0_[m_ + 8];               \
            aC_[bd_][2] = pc1_[m_];  aC_[bd_][3] = pc1_[m_ + 8];               \
            aR_[bd_][0] = pr0_[m_];  aR_[bd_][1] = pr0_[m_ + 8];               \
            aR_[bd_][2] = pr1_[m_];  aR_[bd_][3] = pr1_[m_ + 8];               \
        }                                                                      \
        unsigned bc0_[4], bc1_[4], bi0_[4], bi1_[4];                           \
        _Pragma("unroll")                                                      \
        for (int j_ = 0; j_ < 4; j_++) {                                       \
            const int n_ = n0w + j_ * 8 + g;                                   \
            bc0_[j_] = pc0_[n_];  bc1_[j_] = pc1_[n_];                         \
            bi0_[j_] = pi0_[n_];  bi1_[j_] = pi1_[n_];                         \
        }                                                                      \
        _Pragma("unroll")                                                      \
        for (int bd_ = 0; bd_ < 2; bd_++)                                      \
            _Pragma("unroll")                                                  \
            for (int j_ = 0; j_ < 4; j_++) {                                   \
                mma_f16(accG[bd_][j_], aC_[bd_][0], aC_[bd_][1],               \
                        aC_[bd_][2], aC_[bd_][3], bc0_[j_], bc1_[j_]);         \
                mma_f16(accM[bd_][j_], aR_[bd_][0], aR_[bd_][1],               \
                        aR_[bd_][2], aR_[bd_][3], bi0_[j_], bi1_[j_]);         \
            }                                                                  \
    } while (0)

    // ---- prologue: stage 0 into buffer 0 ----
    LOADC(0, 0); STSC(0, 0);
    LOADC(0, 1); STSC(0, 1);
    __syncthreads();

#pragma unroll 1
    for (int st = 0; st < NSTAGE; st++) {
        const int cur = st & 1;
        const int nxt = cur ^ 1;
        const bool more = (st + 1 < NSTAGE);
        const unsigned* cR = sw + cur * 3 * MATW;
        const unsigned* cI = cR + MATW;
        const unsigned* cC = cI + MATW;

        if (more) LOADC(st + 1, 0);
        COMP(cR, cI, cC, 0);
        if (more) { STSC(nxt, 0); LOADC(st + 1, 1); }
        COMP(cR, cI, cC, 1);
        if (more) STSC(nxt, 1);
        __syncthreads();
    }

    // ---- epilogue: stage G and M through smem, combine, write f16x2 partials ----
    // C frag map: c0:(r,2t) c1:(r,2t+1) c2:(r+8,2t) c3:(r+8,2t+1)
    float* const sA = s_raw;             // [64][65] G
    float* const sM = s_raw + ND * 65;   // [64][65] M
#pragma unroll
    for (int bd = 0; bd < 2; bd++)
#pragma unroll
        for (int jj = 0; jj < 4; jj++) {
            const int r0 = m0w + bd * 16 + g;
            const int r1 = r0 + 8;
            const int n  = n0w + jj * 8 + 2 * t;
            sA[r0 * 65 + n]     = accG[bd][jj][0];
            sA[r0 * 65 + n + 1] = accG[bd][jj][1];
            sA[r1 * 65 + n]     = accG[bd][jj][2];
            sA[r1 * 65 + n + 1] = accG[bd][jj][3];
            sM[r0 * 65 + n]     = accM[bd][jj][0];
            sM[r0 * 65 + n + 1] = accM[bd][jj][1];
            sM[r1 * 65 + n]     = accM[bd][jj][2];
            sM[r1 * 65 + n + 1] = accM[bd][jj][3];
        }
    __syncthreads();

    unsigned* const base = g_scratch + ((long)(sp * NB + b) * 2 << 11);
#pragma unroll
    for (int it = 0; it < 8; it++) {
        const int idx  = it * 128 + tid;   // 0..1023
        const int row  = idx >> 4;
        const int col4 = idx & 15;         // float4 column group
        const int col  = col4 * 4;
        float v0[4], v1[4];
        // mat0 = G - M - M^T (= rr + ii), mat1 = M - M^T (= ri - ri^T).
#pragma unroll
        for (int e = 0; e < 4; e++) {
            const float mm = sM[row * 65 + col + e];
            const float mt = sM[(col + e) * 65 + row];
            const float gg = sA[row * 65 + col + e];
            v0[e] = gg - mm - mt;
            v1[e] = mm - mt;
        }
        *(uint2*)(base +        row * 32 + col4 * 2) =
            make_uint2(pk(v0[0], v0[1]), pk(v0[2], v0[3]));
        *(uint2*)(base + 2048 + row * 32 + col4 * 2) =
            make_uint2(pk(v1[0], v1[1]), pk(v1[2], v1[3]));
    }
}

__global__ __launch_bounds__(256) void reduce_kernel(float* __restrict__ out) {
    // One half2 word (2 floats) per thread: 131072 threads, branch-free.
    const int f   = blockIdx.x * blockDim.x + threadIdx.x;
    const int b   = f >> 12;        // 4096 half2-words per batch (2 mats)
    const int rem = f & 4095;
    const int m   = rem >> 11;      // 0 = real, 1 = imag (uniform per block)
    const int ij2 = rem & 2047;     // half2 index within 64x64 matrix

    const unsigned* p = g_scratch + (((long)(b * 2 + m)) << 11) + ij2;
    float ax = 0.f, ay = 0.f;
#pragma unroll
    for (int sp = 0; sp < NSPLIT; sp++) {
        const unsigned w = __ldcg(p + (long)sp * (NB * 2 * 2048));
        const __half2 h = *(const __half2*)&w;
        const float2 v = __half22float2(h);
        ax += v.x; ay += v.y;
    }
    const float inv = 1.0f / (float)NS;
    *(float2*)(out + (long)m * (NB * ND * ND) + b * (ND * ND) + ij2 * 2) =
        make_float2(ax * inv, ay * inv);
}

extern "C" void kernel_launch(void* const* d_in, const int* in_sizes, int n_in,
                              void* d_out, int out_size) {
    const float* input_real = (const float*)d_in[0];
    const float* input_imag = (const float*)d_in[1];
    float* out = (float*)d_out;

    gram_kernel<<<NB * NSPLIT, 128>>>(input_real, input_imag);
    reduce_kernel<<<512, 256>>>(out);

    (void)in_sizes; (void)n_in; (void)out_size;
}